// round 4
// baseline (speedup 1.0000x reference)
#include <cuda_runtime.h>

// Problem constants (fixed by the dataset instance)
#define BB   2048     // batch
#define TT   2048     // timesteps
#define HH   51       // hidden size
#define G4   204      // 4*H gate rows
#define GP   208      // padded gate count (float4-friendly, stride 52 float4)
#define K1   52       // layer1 K (x + h1)
#define K2   102      // layer2 K (h1 + h2)
#define HP   20       // hcat row pad in floats (16B-aligned float4 slots)
#define RPB  16       // batch rows per block
#define NBLK (BB / RPB)   // 128 blocks
#define NTHR 256

typedef unsigned long long u64;

__device__ __forceinline__ u64 pk2(float a) {
    u64 r; asm("mov.b64 %0, {%1, %1};" : "=l"(r) : "f"(a)); return r;
}
__device__ __forceinline__ u64 fma2(u64 a, u64 b, u64 c) {
    u64 d; asm("fma.rn.f32x2 %0, %1, %2, %3;" : "=l"(d) : "l"(a), "l"(b), "l"(c)); return d;
}
union U2 { u64 v; float2 f; };

__device__ __forceinline__ float sigx(float x) {
    // 1/(1+e^-x): EX2 + RCP, ~1-2 ulp
    return __fdividef(1.0f, 1.0f + __expf(-x));
}
__device__ __forceinline__ float tanhx(float x) {
    // 2/(1+e^-2x) - 1
    return __fdividef(2.0f, 1.0f + __expf(-2.0f * x)) - 1.0f;
}

// dynamic smem layout (floats):
//   W1s  [K1][GP]   : [k][u*4+g], k=0 is the x weight, k=1..51 are Whh1
//   W2s  [K2][GP]   : k=0..50 Wih2, k=51..101 Whh2
//   hcat [K2][HP]   : rows 0..50 = h1[unit][row], rows 51..101 = h2[unit][row]
//   bs1  [GP], bs2 [GP] : combined biases, layout u*4+g
//   wls  [52]       : W_lin (+ pad)
#define SM_W1   0
#define SM_W2   (SM_W1 + K1*GP)
#define SM_H    (SM_W2 + K2*GP)
#define SM_B1   (SM_H  + K2*HP)
#define SM_B2   (SM_B1 + GP)
#define SM_WL   (SM_B2 + GP)
#define SM_TOT  (SM_WL + 52)

__global__ __launch_bounds__(NTHR, 1)
void lstm2_kernel(const float* __restrict__ input,
                  const float* __restrict__ Wih1, const float* __restrict__ Whh1,
                  const float* __restrict__ bih1, const float* __restrict__ bhh1,
                  const float* __restrict__ Wih2, const float* __restrict__ Whh2,
                  const float* __restrict__ bih2, const float* __restrict__ bhh2,
                  const float* __restrict__ Wlin, const float* __restrict__ blin,
                  float* __restrict__ out)
{
    extern __shared__ float sm[];
    float* W1s  = sm + SM_W1;
    float* W2s  = sm + SM_W2;
    float* hcat = sm + SM_H;
    float* bs1  = sm + SM_B1;
    float* bs2  = sm + SM_B2;
    float* wls  = sm + SM_WL;

    const int tid  = threadIdx.x;
    const int row0 = blockIdx.x * RPB;

    // ---- one-time weight staging into smem ----
    for (int idx = tid; idx < K1 * G4; idx += NTHR) {
        int k = idx / G4, c = idx % G4;
        int u = c >> 2, g = c & 3, j = g * HH + u;   // PyTorch gate order i,f,g,o
        W1s[k * GP + c] = (k == 0) ? Wih1[j] : Whh1[j * HH + (k - 1)];
    }
    for (int idx = tid; idx < K2 * G4; idx += NTHR) {
        int k = idx / G4, c = idx % G4;
        int u = c >> 2, g = c & 3, j = g * HH + u;
        W2s[k * GP + c] = (k < HH) ? Wih2[j * HH + k] : Whh2[j * HH + (k - HH)];
    }
    for (int c = tid; c < GP; c += NTHR) {
        if (c < G4) {
            int u = c >> 2, g = c & 3, j = g * HH + u;
            bs1[c] = bih1[j] + bhh1[j];
            bs2[c] = bih2[j] + bhh2[j];
        } else { bs1[c] = 0.0f; bs2[c] = 0.0f; }
    }
    if (tid < HH) wls[tid] = Wlin[tid];
    for (int i = tid; i < K2 * HP; i += NTHR) hcat[i] = 0.0f;  // h1=h2=0 initial state
    __syncthreads();

    // ---- thread roles ----
    const bool cw = (tid < G4);            // gate/channel worker
    int u = 0, rg = 0;
    if (cw) { u = tid % HH; rg = tid / HH; }     // unit u, row group rg (4 rows)
    const bool yw = (tid >= 224 && tid < 240);   // warp 7 lanes 0..15: output proj
    const int  yr = tid - 224;

    const float ybias = blin[0];

    // per-thread persistent cell state (4 rows each)
    float c1[4] = {0.f, 0.f, 0.f, 0.f};
    float c2[4] = {0.f, 0.f, 0.f, 0.f};

    const float4* w1p = reinterpret_cast<const float4*>(W1s) + u;  // [k*52]
    const float4* w2p = reinterpret_cast<const float4*>(W2s) + u;
    float* h1w = &hcat[u * HP + rg * 4];            // this thread's h1 slot
    float* h2w = &hcat[(HH + u) * HP + rg * 4];     // this thread's h2 slot
    const float* xb = input + (row0 + rg * 4) * TT; // x base for row rg*4

    for (int t = 0; t < TT; t++) {
        U2 acc[4][2];
        float h1n[4], h2n[4];

        // ================= layer 1 gates + update =================
        if (cw) {
            float xv0 = __ldg(xb + t);
            float xv1 = __ldg(xb + TT + t);
            float xv2 = __ldg(xb + 2 * TT + t);
            float xv3 = __ldg(xb + 3 * TT + t);

            float4 b4 = *reinterpret_cast<const float4*>(&bs1[u * 4]);
            acc[0][0].v = pk2(b4.x); acc[0][1].v = acc[0][0].v;
            acc[1][0].v = pk2(b4.y); acc[1][1].v = acc[1][0].v;
            acc[2][0].v = pk2(b4.z); acc[2][1].v = acc[2][0].v;
            acc[3][0].v = pk2(b4.w); acc[3][1].v = acc[3][0].v;

            #pragma unroll 3
            for (int k = 1; k <= HH; k++) {
                float4 wv = w1p[k * (GP / 4)];
                ulonglong2 hv = *reinterpret_cast<const ulonglong2*>(&hcat[(k - 1) * HP + rg * 4]);
                u64 w0 = pk2(wv.x), w1 = pk2(wv.y), w2 = pk2(wv.z), w3 = pk2(wv.w);
                acc[0][0].v = fma2(w0, hv.x, acc[0][0].v);
                acc[0][1].v = fma2(w0, hv.y, acc[0][1].v);
                acc[1][0].v = fma2(w1, hv.x, acc[1][0].v);
                acc[1][1].v = fma2(w1, hv.y, acc[1][1].v);
                acc[2][0].v = fma2(w2, hv.x, acc[2][0].v);
                acc[2][1].v = fma2(w2, hv.y, acc[2][1].v);
                acc[3][0].v = fma2(w3, hv.x, acc[3][0].v);
                acc[3][1].v = fma2(w3, hv.y, acc[3][1].v);
            }
            // x contribution (k=0 weight row)
            {
                float4 wv = w1p[0];
                U2 x01, x23; x01.f = make_float2(xv0, xv1); x23.f = make_float2(xv2, xv3);
                u64 w0 = pk2(wv.x), w1 = pk2(wv.y), w2 = pk2(wv.z), w3 = pk2(wv.w);
                acc[0][0].v = fma2(w0, x01.v, acc[0][0].v);
                acc[0][1].v = fma2(w0, x23.v, acc[0][1].v);
                acc[1][0].v = fma2(w1, x01.v, acc[1][0].v);
                acc[1][1].v = fma2(w1, x23.v, acc[1][1].v);
                acc[2][0].v = fma2(w2, x01.v, acc[2][0].v);
                acc[2][1].v = fma2(w2, x23.v, acc[2][1].v);
                acc[3][0].v = fma2(w3, x01.v, acc[3][0].v);
                acc[3][1].v = fma2(w3, x23.v, acc[3][1].v);
            }
            #pragma unroll
            for (int p = 0; p < 2; p++) {
                float2 gi = acc[0][p].f, gf = acc[1][p].f, gg = acc[2][p].f, go = acc[3][p].f;
                int i0 = p * 2;
                float cn = sigx(gf.x) * c1[i0] + sigx(gi.x) * tanhx(gg.x);
                c1[i0] = cn; h1n[i0] = sigx(go.x) * tanhx(cn);
                cn = sigx(gf.y) * c1[i0 + 1] + sigx(gi.y) * tanhx(gg.y);
                c1[i0 + 1] = cn; h1n[i0 + 1] = sigx(go.y) * tanhx(cn);
            }
        }
        __syncthreads();   // all readers of old h1 done
        if (cw) *reinterpret_cast<float4*>(h1w) = make_float4(h1n[0], h1n[1], h1n[2], h1n[3]);
        __syncthreads();   // new h1 visible

        // ================= layer 2 gates + update =================
        if (cw) {
            float4 b4 = *reinterpret_cast<const float4*>(&bs2[u * 4]);
            acc[0][0].v = pk2(b4.x); acc[0][1].v = acc[0][0].v;
            acc[1][0].v = pk2(b4.y); acc[1][1].v = acc[1][0].v;
            acc[2][0].v = pk2(b4.z); acc[2][1].v = acc[2][0].v;
            acc[3][0].v = pk2(b4.w); acc[3][1].v = acc[3][0].v;

            #pragma unroll 3
            for (int k = 0; k < K2; k++) {   // rows 0..50 = new h1, 51..101 = old h2
                float4 wv = w2p[k * (GP / 4)];
                ulonglong2 hv = *reinterpret_cast<const ulonglong2*>(&hcat[k * HP + rg * 4]);
                u64 w0 = pk2(wv.x), w1 = pk2(wv.y), w2 = pk2(wv.z), w3 = pk2(wv.w);
                acc[0][0].v = fma2(w0, hv.x, acc[0][0].v);
                acc[0][1].v = fma2(w0, hv.y, acc[0][1].v);
                acc[1][0].v = fma2(w1, hv.x, acc[1][0].v);
                acc[1][1].v = fma2(w1, hv.y, acc[1][1].v);
                acc[2][0].v = fma2(w2, hv.x, acc[2][0].v);
                acc[2][1].v = fma2(w2, hv.y, acc[2][1].v);
                acc[3][0].v = fma2(w3, hv.x, acc[3][0].v);
                acc[3][1].v = fma2(w3, hv.y, acc[3][1].v);
            }
            #pragma unroll
            for (int p = 0; p < 2; p++) {
                float2 gi = acc[0][p].f, gf = acc[1][p].f, gg = acc[2][p].f, go = acc[3][p].f;
                int i0 = p * 2;
                float cn = sigx(gf.x) * c2[i0] + sigx(gi.x) * tanhx(gg.x);
                c2[i0] = cn; h2n[i0] = sigx(go.x) * tanhx(cn);
                cn = sigx(gf.y) * c2[i0 + 1] + sigx(gi.y) * tanhx(gg.y);
                c2[i0 + 1] = cn; h2n[i0 + 1] = sigx(go.y) * tanhx(cn);
            }
        }
        __syncthreads();   // all readers of old h2 done (incl. warp7 phase3 of t-1)
        if (cw) *reinterpret_cast<float4*>(h2w) = make_float4(h2n[0], h2n[1], h2n[2], h2n[3]);
        __syncthreads();   // new h2 visible

        // ================= output projection (warp 7, overlaps next step) =====
        if (yw) {
            float y = ybias;
            #pragma unroll 3
            for (int k = 0; k < HH; k++)
                y += hcat[(HH + k) * HP + yr] * wls[k];
            out[(row0 + yr) * TT + t] = y;
        }
    }
}

extern "C" void kernel_launch(void* const* d_in, const int* in_sizes, int n_in,
                              void* d_out, int out_size) {
    const float* input = (const float*)d_in[0];
    const float* Wih1  = (const float*)d_in[1];
    const float* Whh1  = (const float*)d_in[2];
    const float* bih1  = (const float*)d_in[3];
    const float* bhh1  = (const float*)d_in[4];
    const float* Wih2  = (const float*)d_in[5];
    const float* Whh2  = (const float*)d_in[6];
    const float* bih2  = (const float*)d_in[7];
    const float* bhh2  = (const float*)d_in[8];
    const float* Wlin  = (const float*)d_in[9];
    const float* blin  = (const float*)d_in[10];
    float* out = (float*)d_out;

    const size_t smem = SM_TOT * sizeof(float);   // ~138 KB
    cudaFuncSetAttribute(lstm2_kernel, cudaFuncAttributeMaxDynamicSharedMemorySize, (int)smem);

    lstm2_kernel<<<NBLK, NTHR, smem>>>(input, Wih1, Whh1, bih1, bhh1,
                                       Wih2, Whh2, bih2, bhh2, Wlin, blin, out);
}

// round 5
// speedup vs baseline: 1.0007x; 1.0007x over previous
#include <cuda_runtime.h>

// Problem constants (fixed by the dataset instance)
#define BB   2048     // batch
#define TT   2048     // timesteps
#define HH   51       // hidden size
#define G4   204      // 4*H gate rows
#define GP   208      // padded gate count (float4-friendly, stride 52 float4)
#define K1   52       // layer1 K (x + h1)
#define K2   102      // layer2 K (h1 + h2)
#define HP   20       // hcat row pad in floats (16B-aligned float4 slots)
#define RPB  16       // batch rows per block
#define NBLK (BB / RPB)   // 128 blocks
#define NTHR 256

typedef unsigned long long u64;

__device__ __forceinline__ u64 pk2(float a) {
    u64 r; asm("mov.b64 %0, {%1, %1};" : "=l"(r) : "f"(a)); return r;
}
__device__ __forceinline__ u64 fma2(u64 a, u64 b, u64 c) {
    u64 d; asm("fma.rn.f32x2 %0, %1, %2, %3;" : "=l"(d) : "l"(a), "l"(b), "l"(c)); return d;
}
union U2 { u64 v; float2 f; };

__device__ __forceinline__ float sigx(float x) {
    // 1/(1+e^-x): EX2 + RCP, ~1-2 ulp
    return __fdividef(1.0f, 1.0f + __expf(-x));
}
__device__ __forceinline__ float tanhx(float x) {
    // 2/(1+e^-2x) - 1
    return __fdividef(2.0f, 1.0f + __expf(-2.0f * x)) - 1.0f;
}

// dynamic smem layout (floats):
//   W1s  [K1][GP]   : [k][u*4+g], k=0 is the x weight, k=1..51 are Whh1
//   W2s  [K2][GP]   : k=0..50 Wih2, k=51..101 Whh2
//   hcat [K2][HP]   : rows 0..50 = h1[unit][row], rows 51..101 = h2[unit][row]
//   bs1  [GP], bs2 [GP] : combined biases, layout u*4+g
//   wls  [52]       : W_lin (+ pad)
#define SM_W1   0
#define SM_W2   (SM_W1 + K1*GP)
#define SM_H    (SM_W2 + K2*GP)
#define SM_B1   (SM_H  + K2*HP)
#define SM_B2   (SM_B1 + GP)
#define SM_WL   (SM_B2 + GP)
#define SM_TOT  (SM_WL + 52)

__global__ __launch_bounds__(NTHR, 1)
void lstm2_kernel(const float* __restrict__ input,
                  const float* __restrict__ Wih1, const float* __restrict__ Whh1,
                  const float* __restrict__ bih1, const float* __restrict__ bhh1,
                  const float* __restrict__ Wih2, const float* __restrict__ Whh2,
                  const float* __restrict__ bih2, const float* __restrict__ bhh2,
                  const float* __restrict__ Wlin, const float* __restrict__ blin,
                  float* __restrict__ out)
{
    extern __shared__ float sm[];
    float* W1s  = sm + SM_W1;
    float* W2s  = sm + SM_W2;
    float* hcat = sm + SM_H;
    float* bs1  = sm + SM_B1;
    float* bs2  = sm + SM_B2;
    float* wls  = sm + SM_WL;

    const int tid  = threadIdx.x;
    const int row0 = blockIdx.x * RPB;

    // ---- one-time weight staging into smem ----
    for (int idx = tid; idx < K1 * G4; idx += NTHR) {
        int k = idx / G4, c = idx % G4;
        int u = c >> 2, g = c & 3, j = g * HH + u;   // PyTorch gate order i,f,g,o
        W1s[k * GP + c] = (k == 0) ? Wih1[j] : Whh1[j * HH + (k - 1)];
    }
    for (int idx = tid; idx < K2 * G4; idx += NTHR) {
        int k = idx / G4, c = idx % G4;
        int u = c >> 2, g = c & 3, j = g * HH + u;
        W2s[k * GP + c] = (k < HH) ? Wih2[j * HH + k] : Whh2[j * HH + (k - HH)];
    }
    for (int c = tid; c < GP; c += NTHR) {
        if (c < G4) {
            int u = c >> 2, g = c & 3, j = g * HH + u;
            bs1[c] = bih1[j] + bhh1[j];
            bs2[c] = bih2[j] + bhh2[j];
        } else { bs1[c] = 0.0f; bs2[c] = 0.0f; }
    }
    if (tid < HH) wls[tid] = Wlin[tid];
    for (int i = tid; i < K2 * HP; i += NTHR) hcat[i] = 0.0f;  // h1=h2=0 initial state
    __syncthreads();

    // ---- thread roles ----
    const bool cw = (tid < G4);            // gate/channel worker
    int u = 0, rg = 0;
    if (cw) { u = tid % HH; rg = tid / HH; }     // unit u, row group rg (4 rows)
    const bool yw = (tid >= 224 && tid < 240);   // warp 7 lanes 0..15: output proj
    const int  yr = tid - 224;

    const float ybias = blin[0];

    // per-thread persistent cell state (4 rows each)
    float c1[4] = {0.f, 0.f, 0.f, 0.f};
    float c2[4] = {0.f, 0.f, 0.f, 0.f};

    const float4* w1p = reinterpret_cast<const float4*>(W1s) + u;  // [k*52]
    const float4* w2p = reinterpret_cast<const float4*>(W2s) + u;
    float* h1w = &hcat[u * HP + rg * 4];            // this thread's h1 slot
    float* h2w = &hcat[(HH + u) * HP + rg * 4];     // this thread's h2 slot
    const float* xb = input + (row0 + rg * 4) * TT; // x base for row rg*4

    for (int t = 0; t < TT; t++) {
        U2 acc[4][2];
        float h1n[4], h2n[4];

        // ================= layer 1 gates + update =================
        if (cw) {
            float xv0 = __ldg(xb + t);
            float xv1 = __ldg(xb + TT + t);
            float xv2 = __ldg(xb + 2 * TT + t);
            float xv3 = __ldg(xb + 3 * TT + t);

            float4 b4 = *reinterpret_cast<const float4*>(&bs1[u * 4]);
            acc[0][0].v = pk2(b4.x); acc[0][1].v = acc[0][0].v;
            acc[1][0].v = pk2(b4.y); acc[1][1].v = acc[1][0].v;
            acc[2][0].v = pk2(b4.z); acc[2][1].v = acc[2][0].v;
            acc[3][0].v = pk2(b4.w); acc[3][1].v = acc[3][0].v;

            #pragma unroll 3
            for (int k = 1; k <= HH; k++) {
                float4 wv = w1p[k * (GP / 4)];
                ulonglong2 hv = *reinterpret_cast<const ulonglong2*>(&hcat[(k - 1) * HP + rg * 4]);
                u64 w0 = pk2(wv.x), w1 = pk2(wv.y), w2 = pk2(wv.z), w3 = pk2(wv.w);
                acc[0][0].v = fma2(w0, hv.x, acc[0][0].v);
                acc[0][1].v = fma2(w0, hv.y, acc[0][1].v);
                acc[1][0].v = fma2(w1, hv.x, acc[1][0].v);
                acc[1][1].v = fma2(w1, hv.y, acc[1][1].v);
                acc[2][0].v = fma2(w2, hv.x, acc[2][0].v);
                acc[2][1].v = fma2(w2, hv.y, acc[2][1].v);
                acc[3][0].v = fma2(w3, hv.x, acc[3][0].v);
                acc[3][1].v = fma2(w3, hv.y, acc[3][1].v);
            }
            // x contribution (k=0 weight row)
            {
                float4 wv = w1p[0];
                U2 x01, x23; x01.f = make_float2(xv0, xv1); x23.f = make_float2(xv2, xv3);
                u64 w0 = pk2(wv.x), w1 = pk2(wv.y), w2 = pk2(wv.z), w3 = pk2(wv.w);
                acc[0][0].v = fma2(w0, x01.v, acc[0][0].v);
                acc[0][1].v = fma2(w0, x23.v, acc[0][1].v);
                acc[1][0].v = fma2(w1, x01.v, acc[1][0].v);
                acc[1][1].v = fma2(w1, x23.v, acc[1][1].v);
                acc[2][0].v = fma2(w2, x01.v, acc[2][0].v);
                acc[2][1].v = fma2(w2, x23.v, acc[2][1].v);
                acc[3][0].v = fma2(w3, x01.v, acc[3][0].v);
                acc[3][1].v = fma2(w3, x23.v, acc[3][1].v);
            }
            #pragma unroll
            for (int p = 0; p < 2; p++) {
                float2 gi = acc[0][p].f, gf = acc[1][p].f, gg = acc[2][p].f, go = acc[3][p].f;
                int i0 = p * 2;
                float cn = sigx(gf.x) * c1[i0] + sigx(gi.x) * tanhx(gg.x);
                c1[i0] = cn; h1n[i0] = sigx(go.x) * tanhx(cn);
                cn = sigx(gf.y) * c1[i0 + 1] + sigx(gi.y) * tanhx(gg.y);
                c1[i0 + 1] = cn; h1n[i0 + 1] = sigx(go.y) * tanhx(cn);
            }
        }
        __syncthreads();   // all readers of old h1 done
        if (cw) *reinterpret_cast<float4*>(h1w) = make_float4(h1n[0], h1n[1], h1n[2], h1n[3]);
        __syncthreads();   // new h1 visible

        // ================= layer 2 gates + update =================
        if (cw) {
            float4 b4 = *reinterpret_cast<const float4*>(&bs2[u * 4]);
            acc[0][0].v = pk2(b4.x); acc[0][1].v = acc[0][0].v;
            acc[1][0].v = pk2(b4.y); acc[1][1].v = acc[1][0].v;
            acc[2][0].v = pk2(b4.z); acc[2][1].v = acc[2][0].v;
            acc[3][0].v = pk2(b4.w); acc[3][1].v = acc[3][0].v;

            #pragma unroll 3
            for (int k = 0; k < K2; k++) {   // rows 0..50 = new h1, 51..101 = old h2
                float4 wv = w2p[k * (GP / 4)];
                ulonglong2 hv = *reinterpret_cast<const ulonglong2*>(&hcat[k * HP + rg * 4]);
                u64 w0 = pk2(wv.x), w1 = pk2(wv.y), w2 = pk2(wv.z), w3 = pk2(wv.w);
                acc[0][0].v = fma2(w0, hv.x, acc[0][0].v);
                acc[0][1].v = fma2(w0, hv.y, acc[0][1].v);
                acc[1][0].v = fma2(w1, hv.x, acc[1][0].v);
                acc[1][1].v = fma2(w1, hv.y, acc[1][1].v);
                acc[2][0].v = fma2(w2, hv.x, acc[2][0].v);
                acc[2][1].v = fma2(w2, hv.y, acc[2][1].v);
                acc[3][0].v = fma2(w3, hv.x, acc[3][0].v);
                acc[3][1].v = fma2(w3, hv.y, acc[3][1].v);
            }
            #pragma unroll
            for (int p = 0; p < 2; p++) {
                float2 gi = acc[0][p].f, gf = acc[1][p].f, gg = acc[2][p].f, go = acc[3][p].f;
                int i0 = p * 2;
                float cn = sigx(gf.x) * c2[i0] + sigx(gi.x) * tanhx(gg.x);
                c2[i0] = cn; h2n[i0] = sigx(go.x) * tanhx(cn);
                cn = sigx(gf.y) * c2[i0 + 1] + sigx(gi.y) * tanhx(gg.y);
                c2[i0 + 1] = cn; h2n[i0 + 1] = sigx(go.y) * tanhx(cn);
            }
        }
        __syncthreads();   // all readers of old h2 done (incl. warp7 phase3 of t-1)
        if (cw) *reinterpret_cast<float4*>(h2w) = make_float4(h2n[0], h2n[1], h2n[2], h2n[3]);
        __syncthreads();   // new h2 visible

        // ================= output projection (warp 7, overlaps next step) =====
        if (yw) {
            float y = ybias;
            #pragma unroll 3
            for (int k = 0; k < HH; k++)
                y += hcat[(HH + k) * HP + yr] * wls[k];
            out[(row0 + yr) * TT + t] = y;
        }
    }
}

extern "C" void kernel_launch(void* const* d_in, const int* in_sizes, int n_in,
                              void* d_out, int out_size) {
    const float* input = (const float*)d_in[0];
    const float* Wih1  = (const float*)d_in[1];
    const float* Whh1  = (const float*)d_in[2];
    const float* bih1  = (const float*)d_in[3];
    const float* bhh1  = (const float*)d_in[4];
    const float* Wih2  = (const float*)d_in[5];
    const float* Whh2  = (const float*)d_in[6];
    const float* bih2  = (const float*)d_in[7];
    const float* bhh2  = (const float*)d_in[8];
    const float* Wlin  = (const float*)d_in[9];
    const float* blin  = (const float*)d_in[10];
    float* out = (float*)d_out;

    const size_t smem = SM_TOT * sizeof(float);   // ~138 KB
    cudaFuncSetAttribute(lstm2_kernel, cudaFuncAttributeMaxDynamicSharedMemorySize, (int)smem);

    lstm2_kernel<<<NBLK, NTHR, smem>>>(input, Wih1, Whh1, bih1, bhh1,
                                       Wih2, Whh2, bih2, bhh2, Wlin, blin, out);
}